// round 14
// baseline (speedup 1.0000x reference)
#include <cuda_runtime.h>
#include <cuda_fp16.h>
#include <math.h>
#include <stdint.h>

#define Bsz 64
#define Lsz 512
#define Esz 512
#define Hsz 1024
#define NG  4096     // gate-interleaved cols: col = h*4+g (0=f,1=i,2=o,3=u)
#define NCTA 128     // persistent CTAs, one 32-col group each

// ---------------- device scratch ----------------
__device__ float g_ball[NG];
// Wh fp16 frags: [cg 128][kk 64][lane 32][8] (8 = 4 j-tiles x {b0,b1})
__device__ uint32_t g_Whf[(size_t)128 * 64 * 32 * 8];
// Wx fp16 frags: [cg 128][kk 32][lane 32][8]
__device__ uint32_t g_Wxf[(size_t)128 * 32 * 32 * 8];
// x fp16 frags, time-major rows m' = t*64+b: [mt 2048][kk 32][lane 32][4]
__device__ uint32_t g_Axf[(size_t)2048 * 32 * 32 * 4];
// h fp16 fragment-quads: [parity][quad 8192][4]
//   quad(kb,mi,q,klo) = ((kb*4+mi)*8+q)*4+klo ; slot r = s + 2*hi
//   covers (row = mi*16+q+8s, k2 = kb*8+klo+4hi)
__device__ uint32_t g_hf2[2][32768];
// per-(group, mi) warp-granular counters: group g = CTAs [16g,16g+16)
__device__ unsigned g_cntGM[32];

// ---------------- helpers ----------------
__device__ __forceinline__ uint32_t f16pair(float2 v) {
    uint32_t r;
    asm("cvt.rn.f16x2.f32 %0, %1, %2;" : "=r"(r) : "f"(v.y), "f"(v.x));
    return r;
}
__device__ __forceinline__ float fsig(float x) {
    return __fdividef(1.f, 1.f + __expf(-x));
}
__device__ __forceinline__ float fth(float x) {
    return 2.f * __fdividef(1.f, 1.f + __expf(-2.f * x)) - 1.f;
}
#define MMAF16(d, a, b0, b1)                                                \
    asm volatile(                                                           \
        "mma.sync.aligned.m16n8k16.row.col.f32.f16.f16.f32 "                \
        "{%0,%1,%2,%3}, {%4,%5,%6,%7}, {%8,%9}, {%0,%1,%2,%3};"             \
        : "+f"((d)[0]), "+f"((d)[1]), "+f"((d)[2]), "+f"((d)[3])            \
        : "r"((a)[0]), "r"((a)[1]), "r"((a)[2]), "r"((a)[3]),               \
          "r"(b0), "r"(b1))

// ---------------------------------------------------------------------------
// Pack: Wh/Wx fp16 fragments, bias, h0 quads, counters. 8192 x 256.
// ---------------------------------------------------------------------------
__global__ void pack_kernel(const float* __restrict__ Wf, const float* __restrict__ Wi,
                            const float* __restrict__ Wo, const float* __restrict__ Wu,
                            const float* __restrict__ bf, const float* __restrict__ bi,
                            const float* __restrict__ bo, const float* __restrict__ bu,
                            const float* __restrict__ h0)
{
    int idx = blockIdx.x * 256 + threadIdx.x;   // 0 .. 2097151
    // ---- Wh fragments: idx = ((cg*64+kk)*32+lane)*8 + r3 ----
    {
        int r3   = idx & 7;
        int lane = (idx >> 3) & 31;
        int kk   = (idx >> 8) & 63;
        int cg   = idx >> 14;
        int j = r3 >> 1, half = r3 & 1;
        int col = cg * 32 + j * 8 + (lane >> 2);
        int h = col >> 2, g = col & 3;
        int k = kk * 16 + half * 8 + (lane & 3) * 2;
        const float* W = (g == 0) ? Wf : (g == 1) ? Wi : (g == 2) ? Wo : Wu;
        float w0 = W[(size_t)(Esz + k) * Hsz + h];
        float w1 = W[(size_t)(Esz + k + 1) * Hsz + h];
        g_Whf[idx] = f16pair(make_float2(w0, w1));
    }
    // ---- Wx fragments: idx = ((cg*32+kk)*32+lane)*8 + r3 ----
    if (idx < (1 << 20)) {
        int r3   = idx & 7;
        int lane = (idx >> 3) & 31;
        int kk   = (idx >> 8) & 31;
        int cg   = idx >> 13;
        int nt = r3 >> 1, b01 = r3 & 1;
        int col = cg * 32 + nt * 8 + (lane >> 2);
        int h = col >> 2, g = col & 3;
        int k = kk * 16 + (lane & 3) * 2 + b01 * 8;
        const float* W = (g == 0) ? Wf : (g == 1) ? Wi : (g == 2) ? Wo : Wu;
        float w0 = W[(size_t)k * Hsz + h];
        float w1 = W[(size_t)(k + 1) * Hsz + h];
        g_Wxf[idx] = f16pair(make_float2(w0, w1));
    }
    if (idx < NG) {
        int h = idx >> 2, g = idx & 3;
        const float* bb = (g == 0) ? bf : (g == 1) ? bi : (g == 2) ? bo : bu;
        g_ball[idx] = bb[h];
    }
    // ---- h0 quads (read by step 0 at parity 1) ----
    if (idx < 32768) {
        int r   = idx & 3;
        int klo = (idx >> 2) & 3;
        int q   = (idx >> 4) & 7;
        int mi  = (idx >> 7) & 3;
        int kb  = idx >> 9;
        int s = r & 1, hi = r >> 1;
        int b = mi * 16 + q + 8 * s;
        int k2 = kb * 8 + klo + 4 * hi;
        g_hf2[1][idx] = f16pair(make_float2(h0[(size_t)b * Hsz + 2 * k2],
                                            h0[(size_t)b * Hsz + 2 * k2 + 1]));
    }
    if (idx < 32) g_cntGM[idx] = 0;
}

// ---------------------------------------------------------------------------
// x -> fp16 fragments, time-major. 32768 x 256 (idx < 2^23).
// ---------------------------------------------------------------------------
__global__ void xsplit_kernel(const float* __restrict__ x)
{
    size_t idx = (size_t)blockIdx.x * 256 + threadIdx.x;
    int r    = (int)(idx & 3);
    int lane = (int)((idx >> 2) & 31);
    int kk   = (int)((idx >> 7) & 31);
    int mt   = (int)(idx >> 12);
    int rowp = mt * 16 + (lane >> 2) + (r & 1) * 8;    // m' = t*64 + b
    int t = rowp >> 6, b = rowp & 63;
    int col = kk * 16 + (lane & 3) * 2 + (r >> 1) * 8;
    float2 v = *(const float2*)(x + ((size_t)b * Lsz + t) * Esz + col);
    g_Axf[idx] = f16pair(v);
}

// ---------------------------------------------------------------------------
// Fused persistent kernel, warp-autonomous: warp = (mi batch-quarter, ng
// col-half), m16 x n16 x full-K. No smem, no __syncthreads in the step loop.
// ---------------------------------------------------------------------------
__global__ __launch_bounds__(256, 1) void lstm_fused_kernel(
    const float* __restrict__ mask, const float* __restrict__ c0,
    float* __restrict__ outh, float* __restrict__ outc)
{
    const int tid = threadIdx.x;
    const int lane = tid & 31, wid = tid >> 5;
    const int mi = wid & 3, ng = wid >> 2;
    const int cg = blockIdx.x;
    const int l3 = lane & 3;
    const int row0 = mi * 16 + (lane >> 2);
    const bool evenp = (l3 & 1) == 0;   // holds f,i of its n-blocks
    const bool lowh  = l3 < 2;          // publishes row0 (else row0+8)

    // this lane's h unit: l3 0->h0(n0), 1->h2(n1), 2->h1(n0), 3->h3(n1)
    const int hloc = ((l3 & 1) << 1) | (l3 >> 1);
    const int hgl = cg * 8 + ng * 4 + hloc;

    float cr0 = c0[(size_t)row0 * Hsz + hgl];
    float cr1 = c0[(size_t)(row0 + 8) * Hsz + hgl];
    const float4 bias = make_float4(g_ball[hgl * 4 + 0], g_ball[hgl * 4 + 1],
                                    g_ball[hgl * 4 + 2], g_ball[hgl * 4 + 3]);

    // publish slot (constant across steps; parity picks the buffer)
    const int k2p = cg * 4 + ng * 2 + (lowh ? l3 : l3 - 2);
    const int bp  = lowh ? row0 : row0 + 8;
    const int kbp = k2p >> 3, klo_p = k2p & 3, hi_p = (k2p >> 2) & 1;
    const int s_p = (bp >> 3) & 1, q_p = bp & 7;
    const size_t widx = ((size_t)((kbp * 4 + mi) * 8 + q_p) * 4 + klo_p) * 4
                        + (s_p + 2 * hi_p);
    const int cidx = (cg >> 4) * 4 + mi;          // producer counter index

    const uint32_t* whb = g_Whf + ((size_t)(cg * 64) * 32 + lane) * 8 + ng * 4;
    const uint32_t* wxb = g_Wxf + ((size_t)(cg * 32) * 32 + lane) * 8 + ng * 4;
    volatile unsigned* vc = (volatile unsigned*)g_cntGM;

    float xr[2][2][4];

    // ---- inline Xg-slice GEMM for step tt -> register ring xr[tt&1] ----
    auto compute_xg = [&](int tt) {
        const int p = tt & 1;
#pragma unroll
        for (int n = 0; n < 2; n++)
#pragma unroll
            for (int q = 0; q < 4; q++) xr[p][n][q] = 0.f;
        const uint32_t* axp = g_Axf + (size_t)(tt * 4 + mi) * 4096 + lane * 4;
        uint4 fa[4], fb[4];
#pragma unroll
        for (int i = 0; i < 4; i++) {
            fa[i] = *(const uint4*)(axp + (size_t)i * 128);
            fb[i] = *(const uint4*)(wxb + (size_t)i * 256);
        }
#pragma unroll
        for (int kk = 0; kk < 32; kk++) {
            uint4 a = fa[kk & 3];
            uint4 b = fb[kk & 3];
            if (kk + 4 < 32) {
                fa[kk & 3] = *(const uint4*)(axp + (size_t)(kk + 4) * 128);
                fb[kk & 3] = *(const uint4*)(wxb + (size_t)(kk + 4) * 256);
            }
            uint32_t ar[4] = {a.x, a.y, a.z, a.w};
            MMAF16(xr[p][0], ar, b.x, b.y);
            MMAF16(xr[p][1], ar, b.z, b.w);
        }
    };

    compute_xg(0);
    compute_xg(1);

    for (int t = 0; t < Lsz; t++) {
        const int tp = t & 1;
        float mk0 = __ldg(mask + (size_t)row0 * Lsz + t);
        float mk1 = __ldg(mask + (size_t)(row0 + 8) * Lsz + t);

        // rec accumulators seeded with this step's xg slice (dual chains)
        float accA[2][4], accB[2][4];
#pragma unroll
        for (int n = 0; n < 2; n++)
#pragma unroll
            for (int q = 0; q < 4; q++) { accA[n][q] = xr[tp][n][q]; accB[n][q] = 0.f; }

        if (t + 2 < Lsz) compute_xg(t + 2);   // overlaps producer tail

        // wait: all producer warp-groups for this warp's batch quarter
        const unsigned tgt = 32u * (unsigned)t;
#pragma unroll
        for (int g = 0; g < 8; g++)
            while (vc[g * 4 + mi] < tgt) __nanosleep(32);

        const uint32_t* hs = g_hf2[(t + 1) & 1] + ((size_t)(mi * 32) + lane) * 4;

        uint4 fA[12];
        uint4 fB[4];
#pragma unroll
        for (int i = 0; i < 12; i++)
            fA[i] = __ldcg((const uint4*)(hs + (size_t)i * 512));
#pragma unroll
        for (int i = 0; i < 4; i++)
            fB[i] = *(const uint4*)(whb + (size_t)i * 256);

#pragma unroll
        for (int it = 0; it < 64; it++) {
            uint4 a = fA[it % 12];
            uint4 b = fB[it & 3];
            if (it + 12 < 64)
                fA[it % 12] = __ldcg((const uint4*)(hs + (size_t)(it + 12) * 512));
            if (it + 4 < 64)
                fB[it & 3] = *(const uint4*)(whb + (size_t)(it + 4) * 256);
            uint32_t ar[4] = {a.x, a.y, a.z, a.w};
            if (it & 1) {
                MMAF16(accB[0], ar, b.x, b.y);
                MMAF16(accB[1], ar, b.z, b.w);
            } else {
                MMAF16(accA[0], ar, b.x, b.y);
                MMAF16(accA[1], ar, b.z, b.w);
            }
        }

        float s[2][4];
#pragma unroll
        for (int n = 0; n < 2; n++)
#pragma unroll
            for (int q = 0; q < 4; q++) s[n][q] = accA[n][q] + accB[n][q];

        // gate exchange: even lane holds f,i; odd holds o,u (per n-block)
        float e0 = evenp ? s[1][0] : s[0][0];
        float e1 = evenp ? s[1][1] : s[0][1];
        float e2 = evenp ? s[1][2] : s[0][2];
        float e3 = evenp ? s[1][3] : s[0][3];
        float r0 = __shfl_xor_sync(0xffffffffu, e0, 1);
        float r1 = __shfl_xor_sync(0xffffffffu, e1, 1);
        float r2 = __shfl_xor_sync(0xffffffffu, e2, 1);
        float r3 = __shfl_xor_sync(0xffffffffu, e3, 1);
        float f0, i0, o0, u0, f1, i1, o1, u1;
        if (evenp) {
            f0 = s[0][0]; i0 = s[0][1]; o0 = r0; u0 = r1;
            f1 = s[0][2]; i1 = s[0][3]; o1 = r2; u1 = r3;
        } else {
            f0 = r0; i0 = r1; o0 = s[1][0]; u0 = s[1][1];
            f1 = r2; i1 = r3; o1 = s[1][2]; u1 = s[1][3];
        }

        float nc0 = fsig(f0 + bias.x) * cr0 + fsig(i0 + bias.y) * fth(u0 + bias.w);
        float nh0 = fsig(o0 + bias.z) * fth(nc0);
        nh0 *= mk0; nc0 *= mk0;
        float nc1 = fsig(f1 + bias.x) * cr1 + fsig(i1 + bias.y) * fth(u1 + bias.w);
        float nh1 = fsig(o1 + bias.z) * fth(nc1);
        nh1 *= mk1; nc1 *= mk1;
        cr0 = nc0; cr1 = nc1;

        // publish fp16 h pair (h_even, h_odd of this lane's k2)
        float ph0 = __shfl_xor_sync(0xffffffffu, nh0, 2);
        float ph1 = __shfl_xor_sync(0xffffffffu, nh1, 2);
        uint32_t pubv = lowh ? f16pair(make_float2(nh0, ph0))
                             : f16pair(make_float2(ph1, nh1));
        g_hf2[tp][widx] = pubv;
        __syncwarp();
        if (lane == 0) {
            __threadfence();
            atomicAdd(&g_cntGM[cidx], 1u);
        }

        // deferred output stores (not on the cross-CTA critical path)
        size_t oi0 = ((size_t)row0 * Lsz + t) * Hsz + hgl;
        size_t oi1 = ((size_t)(row0 + 8) * Lsz + t) * Hsz + hgl;
        outh[oi0] = nh0; outc[oi0] = nc0;
        outh[oi1] = nh1; outc[oi1] = nc1;
    }
}

// ---------------------------------------------------------------------------
extern "C" void kernel_launch(void* const* d_in, const int* in_sizes, int n_in,
                              void* d_out, int out_size)
{
    const float* x    = (const float*)d_in[0];
    const float* mask = (const float*)d_in[1];
    const float* Wf   = (const float*)d_in[2];
    const float* bf   = (const float*)d_in[3];
    const float* Wi   = (const float*)d_in[4];
    const float* bi   = (const float*)d_in[5];
    const float* Wo   = (const float*)d_in[6];
    const float* bo   = (const float*)d_in[7];
    const float* Wu   = (const float*)d_in[8];
    const float* bu   = (const float*)d_in[9];
    const float* h0   = (const float*)d_in[10];
    const float* c0   = (const float*)d_in[11];

    float* outh = (float*)d_out;
    float* outc = outh + (size_t)Bsz * Lsz * Hsz;

    pack_kernel<<<8192, 256>>>(Wf, Wi, Wo, Wu, bf, bi, bo, bu, h0);
    xsplit_kernel<<<32768, 256>>>(x);
    lstm_fused_kernel<<<NCTA, 256>>>(mask, c0, outh, outc);
}

// round 15
// speedup vs baseline: 1.0541x; 1.0541x over previous
#include <cuda_runtime.h>
#include <cuda_fp16.h>
#include <math.h>
#include <stdint.h>

#define Bsz 64
#define Lsz 512
#define Esz 512
#define Hsz 1024
#define NG  4096     // gate-interleaved cols: col = h*4+g (0=f,1=i,2=o,3=u)
#define NCTA 128     // persistent CTAs, one 32-col group each

// smem (floats): gb parity p: gbA = sm + p*4608 (+2304 for B half)   [0, 9216)
//                xg: kh-half base 9216 + kh*9216, 4 slots x 2304     [9216, 27648)
#define SMEM_FLOATS 27648

// ---------------- device scratch ----------------
__device__ float g_ball[NG];
// Wh fp16 frags: [cg 128][kk 64][lane 32][8] (8 = 4 j-tiles x {b0,b1})
__device__ uint32_t g_Whf[(size_t)128 * 64 * 32 * 8];
// Wx fp16 frags: [cg 128][kk 32][lane 32][8]
__device__ uint32_t g_Wxf[(size_t)128 * 32 * 32 * 8];
// x fp16 frags, time-major rows m' = t*64+b: [mt 2048][kk 32][lane 32][4]
__device__ uint32_t g_Axf[(size_t)2048 * 32 * 32 * 4];
// h fp16 fragment-quads: [parity][quad 8192][4]
//   quad(kb,mi,q,klo) = ((kb*4+mi)*8+q)*4+klo ; slot r = s + 2*hi
//   covers (row = mi*16+q+8s, k2 = kb*8+klo+4hi)
__device__ uint32_t g_hf2[2][32768];
// fine-grained step counters, warp-granular: group g = CTAs [16g, 16g+16)
// each producer warp REDs once per step -> 128 arrivals/group/step
__device__ unsigned g_cntG[8];

// ---------------- helpers ----------------
__device__ __forceinline__ uint32_t f16pair(float2 v) {
    uint32_t r;
    asm("cvt.rn.f16x2.f32 %0, %1, %2;" : "=r"(r) : "f"(v.y), "f"(v.x));
    return r;
}
__device__ __forceinline__ float fsig(float x) {
    return __fdividef(1.f, 1.f + __expf(-x));
}
__device__ __forceinline__ float fth(float x) {
    return 2.f * __fdividef(1.f, 1.f + __expf(-2.f * x)) - 1.f;
}
#define MMAF16(d, a, b0, b1)                                                \
    asm volatile(                                                           \
        "mma.sync.aligned.m16n8k16.row.col.f32.f16.f16.f32 "                \
        "{%0,%1,%2,%3}, {%4,%5,%6,%7}, {%8,%9}, {%0,%1,%2,%3};"             \
        : "+f"((d)[0]), "+f"((d)[1]), "+f"((d)[2]), "+f"((d)[3])            \
        : "r"((a)[0]), "r"((a)[1]), "r"((a)[2]), "r"((a)[3]),               \
          "r"(b0), "r"(b1))

// ---------------------------------------------------------------------------
// Pack: Wh/Wx fp16 fragments, bias, h0 quads, counters. 8192 x 256.
// ---------------------------------------------------------------------------
__global__ void pack_kernel(const float* __restrict__ Wf, const float* __restrict__ Wi,
                            const float* __restrict__ Wo, const float* __restrict__ Wu,
                            const float* __restrict__ bf, const float* __restrict__ bi,
                            const float* __restrict__ bo, const float* __restrict__ bu,
                            const float* __restrict__ h0)
{
    int idx = blockIdx.x * 256 + threadIdx.x;   // 0 .. 2097151
    // ---- Wh fragments: idx = ((cg*64+kk)*32+lane)*8 + r3 ----
    {
        int r3   = idx & 7;
        int lane = (idx >> 3) & 31;
        int kk   = (idx >> 8) & 63;
        int cg   = idx >> 14;
        int j = r3 >> 1, half = r3 & 1;
        int col = cg * 32 + j * 8 + (lane >> 2);
        int h = col >> 2, g = col & 3;
        int k = kk * 16 + half * 8 + (lane & 3) * 2;
        const float* W = (g == 0) ? Wf : (g == 1) ? Wi : (g == 2) ? Wo : Wu;
        float w0 = W[(size_t)(Esz + k) * Hsz + h];
        float w1 = W[(size_t)(Esz + k + 1) * Hsz + h];
        g_Whf[idx] = f16pair(make_float2(w0, w1));
    }
    // ---- Wx fragments: idx = ((cg*32+kk)*32+lane)*8 + r3 ----
    if (idx < (1 << 20)) {
        int r3   = idx & 7;
        int lane = (idx >> 3) & 31;
        int kk   = (idx >> 8) & 31;
        int cg   = idx >> 13;
        int nt = r3 >> 1, b01 = r3 & 1;
        int col = cg * 32 + nt * 8 + (lane >> 2);
        int h = col >> 2, g = col & 3;
        int k = kk * 16 + (lane & 3) * 2 + b01 * 8;
        const float* W = (g == 0) ? Wf : (g == 1) ? Wi : (g == 2) ? Wo : Wu;
        float w0 = W[(size_t)k * Hsz + h];
        float w1 = W[(size_t)(k + 1) * Hsz + h];
        g_Wxf[idx] = f16pair(make_float2(w0, w1));
    }
    if (idx < NG) {
        int h = idx >> 2, g = idx & 3;
        const float* bb = (g == 0) ? bf : (g == 1) ? bi : (g == 2) ? bo : bu;
        g_ball[idx] = bb[h];
    }
    // ---- h0 quads (read by step 0 at parity 1) ----
    if (idx < 32768) {
        int r   = idx & 3;
        int klo = (idx >> 2) & 3;
        int q   = (idx >> 4) & 7;
        int mi  = (idx >> 7) & 3;
        int kb  = idx >> 9;
        int s = r & 1, hi = r >> 1;
        int b = mi * 16 + q + 8 * s;
        int k2 = kb * 8 + klo + 4 * hi;
        g_hf2[1][idx] = f16pair(make_float2(h0[(size_t)b * Hsz + 2 * k2],
                                            h0[(size_t)b * Hsz + 2 * k2 + 1]));
    }
    if (idx < 8) g_cntG[idx] = 0;
}

// ---------------------------------------------------------------------------
// x -> fp16 fragments, time-major. 32768 x 256 (idx < 2^23).
// ---------------------------------------------------------------------------
__global__ void xsplit_kernel(const float* __restrict__ x)
{
    size_t idx = (size_t)blockIdx.x * 256 + threadIdx.x;
    int r    = (int)(idx & 3);
    int lane = (int)((idx >> 2) & 31);
    int kk   = (int)((idx >> 7) & 31);
    int mt   = (int)(idx >> 12);
    int rowp = mt * 16 + (lane >> 2) + (r & 1) * 8;    // m' = t*64 + b
    int t = rowp >> 6, b = rowp & 63;
    int col = kk * 16 + (lane & 3) * 2 + (r >> 1) * 8;
    float2 v = *(const float2*)(x + ((size_t)b * Lsz + t) * Esz + col);
    g_Axf[idx] = f16pair(v);
}

// ---------------------------------------------------------------------------
// Fused persistent kernel: recurrence + inline Xg slice, fp16 single-pass,
// fine-grained producer groups, warp-granular release (single CTA barrier).
// ---------------------------------------------------------------------------
__global__ __launch_bounds__(256, 1) void lstm_fused_kernel(
    const float* __restrict__ mask, const float* __restrict__ c0,
    float* __restrict__ outh, float* __restrict__ outc)
{
    extern __shared__ float sm[];

    const int tid = threadIdx.x;
    const int lane = tid & 31, wid = tid >> 5;
    const int mi = wid & 3, kh = wid >> 2;
    const int cg = blockIdx.x;
    const int grp = cg >> 4;                       // this CTA's producer group

    const int pb = tid >> 2;
    const int hu = (tid & 3) * 2;
    const int k2g = cg * 4 + (tid & 3);
    float cr0 = c0[(size_t)pb * Hsz + cg * 8 + hu];
    float cr1 = c0[(size_t)pb * Hsz + cg * 8 + hu + 1];

    const int row0 = mi * 16 + (lane >> 2);
    const int kofs = (lane & 3) * 2;
    const uint32_t* whb = g_Whf + ((size_t)(cg * 64 + kh * 32) * 32 + lane) * 8;
    const uint32_t* wxb = g_Wxf + ((size_t)(cg * 32 + kh * 16) * 32 + lane) * 8;
    const int cbase = (tid & 3) * 8;
    const float4 bias0 = *(const float4*)(g_ball + cg * 32 + cbase);
    const float4 bias1 = *(const float4*)(g_ball + cg * 32 + cbase + 4);

    // writer slot in fragment-quad layout
    const int kb_w = k2g >> 3, klo_w = k2g & 3, hi_w = (k2g >> 2) & 1;
    const int mi_w = pb >> 4, q_w = pb & 7, s_w = (pb >> 3) & 1;
    const size_t widx = ((size_t)((kb_w * 4 + mi_w) * 8 + q_w) * 4 + klo_w) * 4
                        + (s_w + 2 * hi_w);

    // reader base offset (uint32) at it=0: quad (kb=kh*32, mi), lane
    const size_t hroff = ((size_t)((kh * 32 * 4 + mi)) * 32 + lane) * 4;

    // ---- inline Xg-slice GEMM for step tt -> smem ring slot tt&3 ----
    auto compute_xg = [&](int tt) {
        int slot = tt & 3;
        float* xb = sm + 9216 + (kh ? 9216 : 0) + slot * 2304;
        const uint32_t* axp = g_Axf + ((size_t)((tt * 4 + mi) * 32 + kh * 16) * 32 + lane) * 4;
        float xacc[4][4];
#pragma unroll
        for (int n = 0; n < 4; n++)
#pragma unroll
            for (int q = 0; q < 4; q++) xacc[n][q] = 0.f;

        uint4 fa[2], q0[2], q1[2];
        auto loadx = [&](int s, int k) {
            fa[s] = __ldcg((const uint4*)(axp + k * 128));
            q0[s] = *(const uint4*)(wxb + k * 256);
            q1[s] = *(const uint4*)(wxb + k * 256 + 4);
        };
        loadx(0, 0); loadx(1, 1);
#pragma unroll 4
        for (int kkl = 0; kkl < 16; kkl++) {
            const int cur = kkl & 1;
            uint32_t ua[4] = {fa[cur].x, fa[cur].y, fa[cur].z, fa[cur].w};
            uint4 b0 = q0[cur], b1 = q1[cur];
            if (kkl + 2 < 16) loadx(cur, kkl + 2);
            MMAF16(xacc[0], ua, b0.x, b0.y);
            MMAF16(xacc[1], ua, b0.z, b0.w);
            MMAF16(xacc[2], ua, b1.x, b1.y);
            MMAF16(xacc[3], ua, b1.z, b1.w);
        }
#pragma unroll
        for (int nt = 0; nt < 4; nt++) {
            int jc = nt * 8 + kofs;
            *(float2*)&xb[row0 * 36 + jc]       = make_float2(xacc[nt][0], xacc[nt][1]);
            *(float2*)&xb[(row0 + 8) * 36 + jc] = make_float2(xacc[nt][2], xacc[nt][3]);
        }
    };

    compute_xg(0);
    compute_xg(1);

    for (int t = 0; t < Lsz; t++) {
        if (t + 2 < Lsz) compute_xg(t + 2);
        const unsigned tgt = 128u * (unsigned)t;       // warp-granular arrivals
        const uint32_t* hs = g_hf2[(t + 1) & 1] + hroff;
        float mk = __ldg(mask + (size_t)pb * Lsz + t);   // off critical path

        float acc[4][4];
#pragma unroll
        for (int j = 0; j < 4; j++)
#pragma unroll
            for (int q = 0; q < 4; q++) acc[j][q] = 0.f;

        uint4 fA[16];
        uint4 fB[2][2];
        auto loadB = [&](int s, int it) {
            const uint32_t* bp = whb + (size_t)it * 256;
            fB[s][0] = *(const uint4*)bp;
            fB[s][1] = *(const uint4*)(bp + 4);
        };

        // stage 0: wait its 16 producer CTAs (128 warps), launch its 8 A-quads
        while (((volatile unsigned*)g_cntG)[4 * kh] < tgt) __nanosleep(32);
#pragma unroll
        for (int i = 0; i < 8; i++)
            fA[i] = __ldcg((const uint4*)(hs + (size_t)i * 512));
        loadB(0, 0); loadB(1, 1);

#pragma unroll
        for (int gi = 0; gi < 4; gi++) {
            if (gi < 3) {
                while (((volatile unsigned*)g_cntG)[4 * kh + gi + 1] < tgt) __nanosleep(32);
#pragma unroll
                for (int i = 0; i < 8; i++) {
                    int it2 = (gi + 1) * 8 + i;
                    fA[it2 & 15] = __ldcg((const uint4*)(hs + (size_t)it2 * 512));
                }
            }
#pragma unroll
            for (int i = 0; i < 8; i++) {
                const int it = gi * 8 + i;
                const int ca = it & 15, cb = it & 1;
                uint32_t ah[4] = {fA[ca].x, fA[ca].y, fA[ca].z, fA[ca].w};
                uint4 q0 = fB[cb][0], q1 = fB[cb][1];
                if (it + 2 < 32) loadB(cb, it + 2);
                MMAF16(acc[0], ah, q0.x, q0.y);
                MMAF16(acc[1], ah, q0.z, q0.w);
                MMAF16(acc[2], ah, q1.x, q1.y);
                MMAF16(acc[3], ah, q1.z, q1.w);
            }
        }

        // gbuf double-buffered by step parity (WAR-safe under 1-step warp drift)
        float* gbA = sm + (t & 1) * 4608;
        float* gbB = gbA + 2304;
        {
            float* gb = (kh == 0) ? gbA : gbB;
#pragma unroll
            for (int j = 0; j < 4; j++) {
                int jc = j * 8 + kofs;
                *(float2*)&gb[row0 * 36 + jc]       = make_float2(acc[j][0], acc[j][1]);
                *(float2*)&gb[(row0 + 8) * 36 + jc] = make_float2(acc[j][2], acc[j][3]);
            }
        }
        __syncthreads();   // the single CTA barrier: gbuf ready for epilogue

        // fused gates / cell update; publish h quad, warp-granular release
        {
            int slot = t & 3;
            const float* xA = sm + 9216 + slot * 2304 + pb * 36 + cbase;
            const float* xB = xA + 9216;
            float4 xa0 = *(const float4*)xA;
            float4 xa1 = *(const float4*)(xA + 4);
            float4 xb0 = *(const float4*)xB;
            float4 xb1 = *(const float4*)(xB + 4);
            float4 a0 = *(const float4*)&gbA[pb * 36 + cbase];
            float4 a1 = *(const float4*)&gbA[pb * 36 + cbase + 4];
            float4 b0 = *(const float4*)&gbB[pb * 36 + cbase];
            float4 b1 = *(const float4*)&gbB[pb * 36 + cbase + 4];

            float p0 = xa0.x + xb0.x + a0.x + b0.x + bias0.x;
            float p1 = xa0.y + xb0.y + a0.y + b0.y + bias0.y;
            float p2 = xa0.z + xb0.z + a0.z + b0.z + bias0.z;
            float p3 = xa0.w + xb0.w + a0.w + b0.w + bias0.w;
            float nc0 = fsig(p0) * cr0 + fsig(p1) * fth(p3);
            float nh0 = fsig(p2) * fth(nc0);
            nh0 *= mk; nc0 *= mk;

            float q0 = xa1.x + xb1.x + a1.x + b1.x + bias1.x;
            float q1 = xa1.y + xb1.y + a1.y + b1.y + bias1.y;
            float q2 = xa1.z + xb1.z + a1.z + b1.z + bias1.z;
            float q3 = xa1.w + xb1.w + a1.w + b1.w + bias1.w;
            float nc1 = fsig(q0) * cr1 + fsig(q1) * fth(q3);
            float nh1 = fsig(q2) * fth(nc1);
            nh1 *= mk; nc1 *= mk;

            cr0 = nc0; cr1 = nc1;

            // publish split h, then warp-granular release (no CTA barrier)
            g_hf2[t & 1][widx] = f16pair(make_float2(nh0, nh1));
            __syncwarp();
            if (lane == 0) {
                __threadfence();                  // cumulative: releases warp's publishes
                atomicAdd(&g_cntG[grp], 1u);      // no-return -> RED
            }

            // deferred output stores (fully off the cross-CTA critical path)
            size_t oi = ((size_t)pb * Lsz + t) * Hsz + cg * 8 + hu;
            *(float2*)(outh + oi) = make_float2(nh0, nh1);
            *(float2*)(outc + oi) = make_float2(nc0, nc1);
        }
    }
}

// ---------------------------------------------------------------------------
extern "C" void kernel_launch(void* const* d_in, const int* in_sizes, int n_in,
                              void* d_out, int out_size)
{
    const float* x    = (const float*)d_in[0];
    const float* mask = (const float*)d_in[1];
    const float* Wf   = (const float*)d_in[2];
    const float* bf   = (const float*)d_in[3];
    const float* Wi   = (const float*)d_in[4];
    const float* bi   = (const float*)d_in[5];
    const float* Wo   = (const float*)d_in[6];
    const float* bo   = (const float*)d_in[7];
    const float* Wu   = (const float*)d_in[8];
    const float* bu   = (const float*)d_in[9];
    const float* h0   = (const float*)d_in[10];
    const float* c0   = (const float*)d_in[11];

    float* outh = (float*)d_out;
    float* outc = outh + (size_t)Bsz * Lsz * Hsz;

    cudaFuncSetAttribute(lstm_fused_kernel,
                         cudaFuncAttributeMaxDynamicSharedMemorySize,
                         SMEM_FLOATS * 4);

    pack_kernel<<<8192, 256>>>(Wf, Wi, Wo, Wu, bf, bi, bo, bu, h0);
    xsplit_kernel<<<32768, 256>>>(x);
    lstm_fused_kernel<<<NCTA, 256, SMEM_FLOATS * 4>>>(mask, c0, outh, outc);
}

// round 16
// speedup vs baseline: 1.1675x; 1.1075x over previous
#include <cuda_runtime.h>
#include <cuda_fp16.h>
#include <math.h>
#include <stdint.h>

#define Bsz 64
#define Lsz 512
#define Esz 512
#define Hsz 1024
#define NG  4096     // gate-interleaved cols: col = h*4+g (0=f,1=i,2=o,3=u)
#define NCTA 128     // persistent CTAs, one 32-col group each

// smem (floats): gbA[64][36] @0, gbB @2304, xgA slots @4608+s*2304, xgB @+6912
#define SMEM_FLOATS 18432

// ---------------- device scratch ----------------
__device__ float g_ball[NG];
// Wh fp16 frags: [cg 128][kk 64][lane 32][8] (8 = 4 j-tiles x {b0,b1})
__device__ uint32_t g_Whf[(size_t)128 * 64 * 32 * 8];
// Wx fp16 frags: [cg 128][kk 32][lane 32][8]
__device__ uint32_t g_Wxf[(size_t)128 * 32 * 32 * 8];
// x fp16 frags, time-major rows m' = t*64+b: [mt 2048][kk 32][lane 32][4]
__device__ uint32_t g_Axf[(size_t)2048 * 32 * 32 * 4];
// h fp16 fragment-quads: [parity][quad 8192][4]
//   quad(kb,mi,q,klo) = ((kb*4+mi)*8+q)*4+klo ; slot r = s + 2*hi
//   covers (row = mi*16+q+8s, k2 = kb*8+klo+4hi)
__device__ uint32_t g_hf2[2][32768];
// fine-grained step counters: group g = CTAs [16g, 16g+16) (produce k2 [64g,64g+64))
__device__ unsigned g_cntG[8];

// ---------------- helpers ----------------
__device__ __forceinline__ uint32_t f16pair(float2 v) {
    uint32_t r;
    asm("cvt.rn.f16x2.f32 %0, %1, %2;" : "=r"(r) : "f"(v.y), "f"(v.x));
    return r;
}
__device__ __forceinline__ float fsig(float x) {
    return __fdividef(1.f, 1.f + __expf(-x));
}
__device__ __forceinline__ float fth(float x) {
    return 2.f * __fdividef(1.f, 1.f + __expf(-2.f * x)) - 1.f;
}
__device__ __forceinline__ unsigned ld_acq(const unsigned* p) {
    unsigned v;
    asm volatile("ld.acquire.gpu.global.u32 %0, [%1];" : "=r"(v) : "l"(p) : "memory");
    return v;
}
__device__ __forceinline__ void red_rel(unsigned* p) {
    asm volatile("red.release.gpu.global.add.u32 [%0], 1;" :: "l"(p) : "memory");
}
#define MMAF16(d, a, b0, b1)                                                \
    asm volatile(                                                           \
        "mma.sync.aligned.m16n8k16.row.col.f32.f16.f16.f32 "                \
        "{%0,%1,%2,%3}, {%4,%5,%6,%7}, {%8,%9}, {%0,%1,%2,%3};"             \
        : "+f"((d)[0]), "+f"((d)[1]), "+f"((d)[2]), "+f"((d)[3])            \
        : "r"((a)[0]), "r"((a)[1]), "r"((a)[2]), "r"((a)[3]),               \
          "r"(b0), "r"(b1))

// ---------------------------------------------------------------------------
// Pack: Wh/Wx fp16 fragments, bias, h0 quads, counters. 8192 x 256.
// ---------------------------------------------------------------------------
__global__ void pack_kernel(const float* __restrict__ Wf, const float* __restrict__ Wi,
                            const float* __restrict__ Wo, const float* __restrict__ Wu,
                            const float* __restrict__ bf, const float* __restrict__ bi,
                            const float* __restrict__ bo, const float* __restrict__ bu,
                            const float* __restrict__ h0)
{
    int idx = blockIdx.x * 256 + threadIdx.x;   // 0 .. 2097151
    // ---- Wh fragments: idx = ((cg*64+kk)*32+lane)*8 + r3 ----
    {
        int r3   = idx & 7;
        int lane = (idx >> 3) & 31;
        int kk   = (idx >> 8) & 63;
        int cg   = idx >> 14;
        int j = r3 >> 1, half = r3 & 1;
        int col = cg * 32 + j * 8 + (lane >> 2);
        int h = col >> 2, g = col & 3;
        int k = kk * 16 + half * 8 + (lane & 3) * 2;
        const float* W = (g == 0) ? Wf : (g == 1) ? Wi : (g == 2) ? Wo : Wu;
        float w0 = W[(size_t)(Esz + k) * Hsz + h];
        float w1 = W[(size_t)(Esz + k + 1) * Hsz + h];
        g_Whf[idx] = f16pair(make_float2(w0, w1));
    }
    // ---- Wx fragments: idx = ((cg*32+kk)*32+lane)*8 + r3 ----
    if (idx < (1 << 20)) {
        int r3   = idx & 7;
        int lane = (idx >> 3) & 31;
        int kk   = (idx >> 8) & 31;
        int cg   = idx >> 13;
        int nt = r3 >> 1, b01 = r3 & 1;
        int col = cg * 32 + nt * 8 + (lane >> 2);
        int h = col >> 2, g = col & 3;
        int k = kk * 16 + (lane & 3) * 2 + b01 * 8;
        const float* W = (g == 0) ? Wf : (g == 1) ? Wi : (g == 2) ? Wo : Wu;
        float w0 = W[(size_t)k * Hsz + h];
        float w1 = W[(size_t)(k + 1) * Hsz + h];
        g_Wxf[idx] = f16pair(make_float2(w0, w1));
    }
    if (idx < NG) {
        int h = idx >> 2, g = idx & 3;
        const float* bb = (g == 0) ? bf : (g == 1) ? bi : (g == 2) ? bo : bu;
        g_ball[idx] = bb[h];
    }
    // ---- h0 quads (read by step 0 at parity 1) ----
    if (idx < 32768) {
        int r   = idx & 3;
        int klo = (idx >> 2) & 3;
        int q   = (idx >> 4) & 7;
        int mi  = (idx >> 7) & 3;
        int kb  = idx >> 9;
        int s = r & 1, hi = r >> 1;
        int b = mi * 16 + q + 8 * s;
        int k2 = kb * 8 + klo + 4 * hi;
        g_hf2[1][idx] = f16pair(make_float2(h0[(size_t)b * Hsz + 2 * k2],
                                            h0[(size_t)b * Hsz + 2 * k2 + 1]));
    }
    if (idx < 8) g_cntG[idx] = 0;
}

// ---------------------------------------------------------------------------
// x -> fp16 fragments, time-major. 32768 x 256 (idx < 2^23).
// ---------------------------------------------------------------------------
__global__ void xsplit_kernel(const float* __restrict__ x)
{
    size_t idx = (size_t)blockIdx.x * 256 + threadIdx.x;
    int r    = (int)(idx & 3);
    int lane = (int)((idx >> 2) & 31);
    int kk   = (int)((idx >> 7) & 31);
    int mt   = (int)(idx >> 12);
    int rowp = mt * 16 + (lane >> 2) + (r & 1) * 8;    // m' = t*64 + b
    int t = rowp >> 6, b = rowp & 63;
    int col = kk * 16 + (lane & 3) * 2 + (r >> 1) * 8;
    float2 v = *(const float2*)(x + ((size_t)b * Lsz + t) * Esz + col);
    g_Axf[idx] = f16pair(v);
}

// ---------------------------------------------------------------------------
// Fused persistent kernel: recurrence + inline Xg slice, fp16 single-pass,
// fine-grained producer groups, mid-stage polls, release-RED signaling.
// ---------------------------------------------------------------------------
__global__ __launch_bounds__(256, 1) void lstm_fused_kernel(
    const float* __restrict__ mask, const float* __restrict__ c0,
    float* __restrict__ outh, float* __restrict__ outc)
{
    extern __shared__ float sm[];

    const int tid = threadIdx.x;
    const int lane = tid & 31, wid = tid >> 5;
    const int mi = wid & 3, kh = wid >> 2;
    const int cg = blockIdx.x;
    const int grp = cg >> 4;                       // this CTA's producer group

    const int pb = tid >> 2;
    const int hu = (tid & 3) * 2;
    const int k2g = cg * 4 + (tid & 3);
    float cr0 = c0[(size_t)pb * Hsz + cg * 8 + hu];
    float cr1 = c0[(size_t)pb * Hsz + cg * 8 + hu + 1];

    const int row0 = mi * 16 + (lane >> 2);
    const int kofs = (lane & 3) * 2;
    const uint32_t* whb = g_Whf + ((size_t)(cg * 64 + kh * 32) * 32 + lane) * 8;
    const uint32_t* wxb = g_Wxf + ((size_t)(cg * 32 + kh * 16) * 32 + lane) * 8;
    const int cbase = (tid & 3) * 8;
    const float4 bias0 = *(const float4*)(g_ball + cg * 32 + cbase);
    const float4 bias1 = *(const float4*)(g_ball + cg * 32 + cbase + 4);

    // writer slot in fragment-quad layout
    const int kb_w = k2g >> 3, klo_w = k2g & 3, hi_w = (k2g >> 2) & 1;
    const int mi_w = pb >> 4, q_w = pb & 7, s_w = (pb >> 3) & 1;
    const size_t widx = ((size_t)((kb_w * 4 + mi_w) * 8 + q_w) * 4 + klo_w) * 4
                        + (s_w + 2 * hi_w);

    // reader base offset (uint32) at it=0: quad (kb=kh*32, mi), lane
    const size_t hroff = ((size_t)((kh * 32 * 4 + mi)) * 32 + lane) * 4;

    float* gbA = sm;
    float* gbB = sm + 2304;

    // ---- inline Xg-slice GEMM for step tt -> smem ring slot tt%3 ----
    auto compute_xg = [&](int tt) {
        int slot = tt % 3;
        float* xb = sm + 4608 + (kh ? 6912 : 0) + slot * 2304;
        const uint32_t* axp = g_Axf + ((size_t)((tt * 4 + mi) * 32 + kh * 16) * 32 + lane) * 4;
        float xacc[4][4];
#pragma unroll
        for (int n = 0; n < 4; n++)
#pragma unroll
            for (int q = 0; q < 4; q++) xacc[n][q] = 0.f;

        uint4 fa[2], q0[2], q1[2];
        auto loadx = [&](int s, int k) {
            fa[s] = __ldcg((const uint4*)(axp + k * 128));
            q0[s] = *(const uint4*)(wxb + k * 256);
            q1[s] = *(const uint4*)(wxb + k * 256 + 4);
        };
        loadx(0, 0); loadx(1, 1);
#pragma unroll 4
        for (int kkl = 0; kkl < 16; kkl++) {
            const int cur = kkl & 1;
            uint32_t ua[4] = {fa[cur].x, fa[cur].y, fa[cur].z, fa[cur].w};
            uint4 b0 = q0[cur], b1 = q1[cur];
            if (kkl + 2 < 16) loadx(cur, kkl + 2);
            MMAF16(xacc[0], ua, b0.x, b0.y);
            MMAF16(xacc[1], ua, b0.z, b0.w);
            MMAF16(xacc[2], ua, b1.x, b1.y);
            MMAF16(xacc[3], ua, b1.z, b1.w);
        }
#pragma unroll
        for (int nt = 0; nt < 4; nt++) {
            int jc = nt * 8 + kofs;
            *(float2*)&xb[row0 * 36 + jc]       = make_float2(xacc[nt][0], xacc[nt][1]);
            *(float2*)&xb[(row0 + 8) * 36 + jc] = make_float2(xacc[nt][2], xacc[nt][3]);
        }
    };

    compute_xg(0);
    compute_xg(1);

    for (int t = 0; t < Lsz; t++) {
        if (t + 2 < Lsz) compute_xg(t + 2);
        const unsigned tgt = 16u * (unsigned)t;
        const uint32_t* hs = g_hf2[(t + 1) & 1] + hroff;
        float mk = __ldg(mask + (size_t)pb * Lsz + t);   // off critical path

        float acc[4][4];
#pragma unroll
        for (int j = 0; j < 4; j++)
#pragma unroll
            for (int q = 0; q < 4; q++) acc[j][q] = 0.f;

        uint4 fA[16];
        uint4 fB[2][2];
        auto loadB = [&](int s, int it) {
            const uint32_t* bp = whb + (size_t)it * 256;
            fB[s][0] = *(const uint4*)bp;
            fB[s][1] = *(const uint4*)(bp + 4);
        };

        // stage 0: wait its 16 producers, launch its 8 A-quads
        while (ld_acq(&g_cntG[4 * kh]) < tgt) __nanosleep(32);
#pragma unroll
        for (int i = 0; i < 8; i++)
            fA[i] = __ldcg((const uint4*)(hs + (size_t)i * 512));
        loadB(0, 0); loadB(1, 1);

#pragma unroll
        for (int gi = 0; gi < 4; gi++) {
            // first 4 iterations of stage gi (ready work hides the next poll)
#pragma unroll
            for (int i = 0; i < 4; i++) {
                const int it = gi * 8 + i;
                const int ca = it & 15, cb = it & 1;
                uint32_t ah[4] = {fA[ca].x, fA[ca].y, fA[ca].z, fA[ca].w};
                uint4 q0 = fB[cb][0], q1 = fB[cb][1];
                if (it + 2 < 32) loadB(cb, it + 2);
                MMAF16(acc[0], ah, q0.x, q0.y);
                MMAF16(acc[1], ah, q0.z, q0.w);
                MMAF16(acc[2], ah, q1.x, q1.y);
                MMAF16(acc[3], ah, q1.z, q1.w);
            }
            // poll next group mid-stage; issue its loads 4 iterations ahead
            if (gi < 3) {
                while (ld_acq(&g_cntG[4 * kh + gi + 1]) < tgt) __nanosleep(32);
#pragma unroll
                for (int i = 0; i < 8; i++) {
                    int it2 = (gi + 1) * 8 + i;
                    fA[it2 & 15] = __ldcg((const uint4*)(hs + (size_t)it2 * 512));
                }
            }
            // remaining 4 iterations of stage gi
#pragma unroll
            for (int i = 4; i < 8; i++) {
                const int it = gi * 8 + i;
                const int ca = it & 15, cb = it & 1;
                uint32_t ah[4] = {fA[ca].x, fA[ca].y, fA[ca].z, fA[ca].w};
                uint4 q0 = fB[cb][0], q1 = fB[cb][1];
                if (it + 2 < 32) loadB(cb, it + 2);
                MMAF16(acc[0], ah, q0.x, q0.y);
                MMAF16(acc[1], ah, q0.z, q0.w);
                MMAF16(acc[2], ah, q1.x, q1.y);
                MMAF16(acc[3], ah, q1.z, q1.w);
            }
        }

        {
            float* gb = (kh == 0) ? gbA : gbB;
#pragma unroll
            for (int j = 0; j < 4; j++) {
                int jc = j * 8 + kofs;
                *(float2*)&gb[row0 * 36 + jc]       = make_float2(acc[j][0], acc[j][1]);
                *(float2*)&gb[(row0 + 8) * 36 + jc] = make_float2(acc[j][2], acc[j][3]);
            }
        }
        __syncthreads();

        // fused gates / cell update; publish h quad, release-RED signal
        {
            int slot = t % 3;
            const float* xA = sm + 4608 + slot * 2304 + pb * 36 + cbase;
            const float* xB = xA + 6912;
            float4 xa0 = *(const float4*)xA;
            float4 xa1 = *(const float4*)(xA + 4);
            float4 xb0 = *(const float4*)xB;
            float4 xb1 = *(const float4*)(xB + 4);
            float4 a0 = *(const float4*)&gbA[pb * 36 + cbase];
            float4 a1 = *(const float4*)&gbA[pb * 36 + cbase + 4];
            float4 b0 = *(const float4*)&gbB[pb * 36 + cbase];
            float4 b1 = *(const float4*)&gbB[pb * 36 + cbase + 4];

            float p0 = xa0.x + xb0.x + a0.x + b0.x + bias0.x;
            float p1 = xa0.y + xb0.y + a0.y + b0.y + bias0.y;
            float p2 = xa0.z + xb0.z + a0.z + b0.z + bias0.z;
            float p3 = xa0.w + xb0.w + a0.w + b0.w + bias0.w;
            float nc0 = fsig(p0) * cr0 + fsig(p1) * fth(p3);
            float nh0 = fsig(p2) * fth(nc0);
            nh0 *= mk; nc0 *= mk;

            float q0 = xa1.x + xb1.x + a1.x + b1.x + bias1.x;
            float q1 = xa1.y + xb1.y + a1.y + b1.y + bias1.y;
            float q2 = xa1.z + xb1.z + a1.z + b1.z + bias1.z;
            float q3 = xa1.w + xb1.w + a1.w + b1.w + bias1.w;
            float nc1 = fsig(q0) * cr1 + fsig(q1) * fth(q3);
            float nh1 = fsig(q2) * fth(nc1);
            nh1 *= mk; nc1 *= mk;

            cr0 = nc0; cr1 = nc1;

            // publish split h (the only cross-CTA-consumed data)
            g_hf2[t & 1][widx] = f16pair(make_float2(nh0, nh1));
            __syncthreads();                      // orders all publishes before tid0's RED
            if (tid == 0) red_rel(&g_cntG[grp]);  // release-RED: no MEMBAR on the path

            // deferred output stores (not on the critical path)
            size_t oi = ((size_t)pb * Lsz + t) * Hsz + cg * 8 + hu;
            *(float2*)(outh + oi) = make_float2(nh0, nh1);
            *(float2*)(outc + oi) = make_float2(nc0, nc1);
        }
    }
}

// ---------------------------------------------------------------------------
extern "C" void kernel_launch(void* const* d_in, const int* in_sizes, int n_in,
                              void* d_out, int out_size)
{
    const float* x    = (const float*)d_in[0];
    const float* mask = (const float*)d_in[1];
    const float* Wf   = (const float*)d_in[2];
    const float* bf   = (const float*)d_in[3];
    const float* Wi   = (const float*)d_in[4];
    const float* bi   = (const float*)d_in[5];
    const float* Wo   = (const float*)d_in[6];
    const float* bo   = (const float*)d_in[7];
    const float* Wu   = (const float*)d_in[8];
    const float* bu   = (const float*)d_in[9];
    const float* h0   = (const float*)d_in[10];
    const float* c0   = (const float*)d_in[11];

    float* outh = (float*)d_out;
    float* outc = outh + (size_t)Bsz * Lsz * Hsz;

    cudaFuncSetAttribute(lstm_fused_kernel,
                         cudaFuncAttributeMaxDynamicSharedMemorySize,
                         SMEM_FLOATS * 4);

    pack_kernel<<<8192, 256>>>(Wf, Wi, Wo, Wu, bf, bi, bo, bu, h0);
    xsplit_kernel<<<32768, 256>>>(x);
    lstm_fused_kernel<<<NCTA, 256, SMEM_FLOATS * 4>>>(mask, c0, outh, outc);
}

// round 17
// speedup vs baseline: 1.3001x; 1.1136x over previous
#include <cuda_runtime.h>
#include <cuda_fp16.h>
#include <math.h>
#include <stdint.h>

#define Bsz 64
#define Lsz 512
#define Esz 512
#define Hsz 1024
#define NG  4096     // gate-interleaved cols: col = h*4+g (0=f,1=i,2=o,3=u)
#define NCTA 128     // persistent CTAs, one 32-col group each

// smem (floats): gbA[64][36] @0, gbB @2304, xgA slots @4608+s*2304, xgB @+6912
#define SMEM_FLOATS 18432

// ---------------- device scratch ----------------
__device__ float g_ball[NG];
// Wh fp16 frags: [cg 128][kk 64][lane 32][8] (8 = 4 j-tiles x {b0,b1})
__device__ uint32_t g_Whf[(size_t)128 * 64 * 32 * 8];
// Wx fp16 frags: [cg 128][kk 32][lane 32][8]
__device__ uint32_t g_Wxf[(size_t)128 * 32 * 32 * 8];
// x fp16 frags, time-major rows m' = t*64+b: [mt 2048][kk 32][lane 32][4]
__device__ uint32_t g_Axf[(size_t)2048 * 32 * 32 * 4];
// h fp16 fragment-quads: [parity][quad 8192][4]
//   quad(kb,mi,q,klo) = ((kb*4+mi)*8+q)*4+klo ; slot r = s + 2*hi
//   covers (row = mi*16+q+8s, k2 = kb*8+klo+4hi)
__device__ uint32_t g_hf2[2][32768];
// fine-grained step counters: group g = CTAs [16g, 16g+16) (produce k2 [64g,64g+64))
__device__ unsigned g_cntG[8];

// ---------------- helpers ----------------
__device__ __forceinline__ uint32_t f16pair(float2 v) {
    uint32_t r;
    asm("cvt.rn.f16x2.f32 %0, %1, %2;" : "=r"(r) : "f"(v.y), "f"(v.x));
    return r;
}
__device__ __forceinline__ float fsig(float x) {
    return __fdividef(1.f, 1.f + __expf(-x));
}
__device__ __forceinline__ float fth(float x) {
    return 2.f * __fdividef(1.f, 1.f + __expf(-2.f * x)) - 1.f;
}
__device__ __forceinline__ unsigned ld_acq(const unsigned* p) {
    unsigned v;
    asm volatile("ld.acquire.gpu.global.u32 %0, [%1];" : "=r"(v) : "l"(p) : "memory");
    return v;
}
__device__ __forceinline__ void red_rel(unsigned* p) {
    asm volatile("red.release.gpu.global.add.u32 [%0], 1;" :: "l"(p) : "memory");
}
#define MMAF16(d, a, b0, b1)                                                \
    asm volatile(                                                           \
        "mma.sync.aligned.m16n8k16.row.col.f32.f16.f16.f32 "                \
        "{%0,%1,%2,%3}, {%4,%5,%6,%7}, {%8,%9}, {%0,%1,%2,%3};"             \
        : "+f"((d)[0]), "+f"((d)[1]), "+f"((d)[2]), "+f"((d)[3])            \
        : "r"((a)[0]), "r"((a)[1]), "r"((a)[2]), "r"((a)[3]),               \
          "r"(b0), "r"(b1))

// ---------------------------------------------------------------------------
// Pack: Wh/Wx fp16 fragments, bias, h0 quads, counters. 8192 x 256.
// ---------------------------------------------------------------------------
__global__ void pack_kernel(const float* __restrict__ Wf, const float* __restrict__ Wi,
                            const float* __restrict__ Wo, const float* __restrict__ Wu,
                            const float* __restrict__ bf, const float* __restrict__ bi,
                            const float* __restrict__ bo, const float* __restrict__ bu,
                            const float* __restrict__ h0)
{
    int idx = blockIdx.x * 256 + threadIdx.x;   // 0 .. 2097151
    // ---- Wh fragments: idx = ((cg*64+kk)*32+lane)*8 + r3 ----
    {
        int r3   = idx & 7;
        int lane = (idx >> 3) & 31;
        int kk   = (idx >> 8) & 63;
        int cg   = idx >> 14;
        int j = r3 >> 1, half = r3 & 1;
        int col = cg * 32 + j * 8 + (lane >> 2);
        int h = col >> 2, g = col & 3;
        int k = kk * 16 + half * 8 + (lane & 3) * 2;
        const float* W = (g == 0) ? Wf : (g == 1) ? Wi : (g == 2) ? Wo : Wu;
        float w0 = W[(size_t)(Esz + k) * Hsz + h];
        float w1 = W[(size_t)(Esz + k + 1) * Hsz + h];
        g_Whf[idx] = f16pair(make_float2(w0, w1));
    }
    // ---- Wx fragments: idx = ((cg*32+kk)*32+lane)*8 + r3 ----
    if (idx < (1 << 20)) {
        int r3   = idx & 7;
        int lane = (idx >> 3) & 31;
        int kk   = (idx >> 8) & 31;
        int cg   = idx >> 13;
        int nt = r3 >> 1, b01 = r3 & 1;
        int col = cg * 32 + nt * 8 + (lane >> 2);
        int h = col >> 2, g = col & 3;
        int k = kk * 16 + (lane & 3) * 2 + b01 * 8;
        const float* W = (g == 0) ? Wf : (g == 1) ? Wi : (g == 2) ? Wo : Wu;
        float w0 = W[(size_t)k * Hsz + h];
        float w1 = W[(size_t)(k + 1) * Hsz + h];
        g_Wxf[idx] = f16pair(make_float2(w0, w1));
    }
    if (idx < NG) {
        int h = idx >> 2, g = idx & 3;
        const float* bb = (g == 0) ? bf : (g == 1) ? bi : (g == 2) ? bo : bu;
        g_ball[idx] = bb[h];
    }
    // ---- h0 quads (read by step 0 at parity 1) ----
    if (idx < 32768) {
        int r   = idx & 3;
        int klo = (idx >> 2) & 3;
        int q   = (idx >> 4) & 7;
        int mi  = (idx >> 7) & 3;
        int kb  = idx >> 9;
        int s = r & 1, hi = r >> 1;
        int b = mi * 16 + q + 8 * s;
        int k2 = kb * 8 + klo + 4 * hi;
        g_hf2[1][idx] = f16pair(make_float2(h0[(size_t)b * Hsz + 2 * k2],
                                            h0[(size_t)b * Hsz + 2 * k2 + 1]));
    }
    if (idx < 8) g_cntG[idx] = 0;
}

// ---------------------------------------------------------------------------
// x -> fp16 fragments, time-major. 32768 x 256 (idx < 2^23).
// ---------------------------------------------------------------------------
__global__ void xsplit_kernel(const float* __restrict__ x)
{
    size_t idx = (size_t)blockIdx.x * 256 + threadIdx.x;
    int r    = (int)(idx & 3);
    int lane = (int)((idx >> 2) & 31);
    int kk   = (int)((idx >> 7) & 31);
    int mt   = (int)(idx >> 12);
    int rowp = mt * 16 + (lane >> 2) + (r & 1) * 8;    // m' = t*64 + b
    int t = rowp >> 6, b = rowp & 63;
    int col = kk * 16 + (lane & 3) * 2 + (r >> 1) * 8;
    float2 v = *(const float2*)(x + ((size_t)b * Lsz + t) * Esz + col);
    g_Axf[idx] = f16pair(v);
}

// ---------------------------------------------------------------------------
// Fused persistent kernel: recurrence + inline Xg slice, fp16 single-pass,
// fine-grained producer groups, mid-stage polls, release-RED signaling,
// xg chunks interleaved with stage-0 readiness checks (A latency hidden).
// ---------------------------------------------------------------------------
__global__ __launch_bounds__(256, 1) void lstm_fused_kernel(
    const float* __restrict__ mask, const float* __restrict__ c0,
    float* __restrict__ outh, float* __restrict__ outc)
{
    extern __shared__ float sm[];

    const int tid = threadIdx.x;
    const int lane = tid & 31, wid = tid >> 5;
    const int mi = wid & 3, kh = wid >> 2;
    const int cg = blockIdx.x;
    const int grp = cg >> 4;                       // this CTA's producer group

    const int pb = tid >> 2;
    const int hu = (tid & 3) * 2;
    const int k2g = cg * 4 + (tid & 3);
    float cr0 = c0[(size_t)pb * Hsz + cg * 8 + hu];
    float cr1 = c0[(size_t)pb * Hsz + cg * 8 + hu + 1];

    const int row0 = mi * 16 + (lane >> 2);
    const int kofs = (lane & 3) * 2;
    const uint32_t* whb = g_Whf + ((size_t)(cg * 64 + kh * 32) * 32 + lane) * 8;
    const uint32_t* wxb = g_Wxf + ((size_t)(cg * 32 + kh * 16) * 32 + lane) * 8;
    const int cbase = (tid & 3) * 8;
    const float4 bias0 = *(const float4*)(g_ball + cg * 32 + cbase);
    const float4 bias1 = *(const float4*)(g_ball + cg * 32 + cbase + 4);

    // writer slot in fragment-quad layout
    const int kb_w = k2g >> 3, klo_w = k2g & 3, hi_w = (k2g >> 2) & 1;
    const int mi_w = pb >> 4, q_w = pb & 7, s_w = (pb >> 3) & 1;
    const size_t widx = ((size_t)((kb_w * 4 + mi_w) * 8 + q_w) * 4 + klo_w) * 4
                        + (s_w + 2 * hi_w);

    // reader base offset (uint32) at it=0: quad (kb=kh*32, mi), lane
    const size_t hroff = ((size_t)((kh * 32 * 4 + mi)) * 32 + lane) * 4;

    float* gbA = sm;
    float* gbB = sm + 2304;

    // ---- full inline Xg-slice GEMM (used only for the pre-loop warmup) ----
    auto compute_xg = [&](int tt) {
        int slot = tt % 3;
        float* xb = sm + 4608 + (kh ? 6912 : 0) + slot * 2304;
        const uint32_t* axp = g_Axf + ((size_t)((tt * 4 + mi) * 32 + kh * 16) * 32 + lane) * 4;
        float xacc[4][4];
#pragma unroll
        for (int n = 0; n < 4; n++)
#pragma unroll
            for (int q = 0; q < 4; q++) xacc[n][q] = 0.f;

        uint4 fa[2], q0[2], q1[2];
        auto loadx = [&](int s, int k) {
            fa[s] = __ldcg((const uint4*)(axp + k * 128));
            q0[s] = *(const uint4*)(wxb + k * 256);
            q1[s] = *(const uint4*)(wxb + k * 256 + 4);
        };
        loadx(0, 0); loadx(1, 1);
#pragma unroll 4
        for (int kkl = 0; kkl < 16; kkl++) {
            const int cur = kkl & 1;
            uint32_t ua[4] = {fa[cur].x, fa[cur].y, fa[cur].z, fa[cur].w};
            uint4 b0 = q0[cur], b1 = q1[cur];
            if (kkl + 2 < 16) loadx(cur, kkl + 2);
            MMAF16(xacc[0], ua, b0.x, b0.y);
            MMAF16(xacc[1], ua, b0.z, b0.w);
            MMAF16(xacc[2], ua, b1.x, b1.y);
            MMAF16(xacc[3], ua, b1.z, b1.w);
        }
#pragma unroll
        for (int nt = 0; nt < 4; nt++) {
            int jc = nt * 8 + kofs;
            *(float2*)&xb[row0 * 36 + jc]       = make_float2(xacc[nt][0], xacc[nt][1]);
            *(float2*)&xb[(row0 + 8) * 36 + jc] = make_float2(xacc[nt][2], xacc[nt][3]);
        }
    };

    compute_xg(0);
    compute_xg(1);

    for (int t = 0; t < Lsz; t++) {
        const unsigned tgt = 16u * (unsigned)t;
        const uint32_t* hs = g_hf2[(t + 1) & 1] + hroff;
        float mk = __ldg(mask + (size_t)pb * Lsz + t);   // off critical path

        uint4 fA[16];
        uint4 fB[2][2];
        auto loadB = [&](int s, int it) {
            const uint32_t* bp = whb + (size_t)it * 256;
            fB[s][0] = *(const uint4*)bp;
            fB[s][1] = *(const uint4*)(bp + 4);
        };
        auto issue_stage0 = [&]() {
#pragma unroll
            for (int i = 0; i < 8; i++)
                fA[i] = __ldcg((const uint4*)(hs + (size_t)i * 512));
            loadB(0, 0); loadB(1, 1);
        };

        bool ready = false;

        // ---- xg(t+2) in 4 chunks, checking stage-0 readiness between chunks ----
        if (t + 2 < Lsz) {
            const int tt = t + 2;
            const int slot = tt % 3;
            float* xb = sm + 4608 + (kh ? 6912 : 0) + slot * 2304;
            const uint32_t* axp = g_Axf + ((size_t)((tt * 4 + mi) * 32 + kh * 16) * 32 + lane) * 4;
            float xacc[4][4];
#pragma unroll
            for (int n = 0; n < 4; n++)
#pragma unroll
                for (int q = 0; q < 4; q++) xacc[n][q] = 0.f;

            uint4 fa[2], q0[2], q1[2];
            auto loadx = [&](int s, int k) {
                fa[s] = __ldcg((const uint4*)(axp + k * 128));
                q0[s] = *(const uint4*)(wxb + k * 256);
                q1[s] = *(const uint4*)(wxb + k * 256 + 4);
            };
            loadx(0, 0); loadx(1, 1);
#pragma unroll
            for (int ch = 0; ch < 4; ch++) {
                // non-blocking readiness check: hide stage-0 A latency under xg
                if (!ready && ld_acq(&g_cntG[4 * kh]) >= tgt) {
                    ready = true;
                    issue_stage0();
                }
#pragma unroll
                for (int i = 0; i < 4; i++) {
                    const int kkl = ch * 4 + i;
                    const int cur = kkl & 1;
                    uint32_t ua[4] = {fa[cur].x, fa[cur].y, fa[cur].z, fa[cur].w};
                    uint4 b0 = q0[cur], b1 = q1[cur];
                    if (kkl + 2 < 16) loadx(cur, kkl + 2);
                    MMAF16(xacc[0], ua, b0.x, b0.y);
                    MMAF16(xacc[1], ua, b0.z, b0.w);
                    MMAF16(xacc[2], ua, b1.x, b1.y);
                    MMAF16(xacc[3], ua, b1.z, b1.w);
                }
            }
#pragma unroll
            for (int nt = 0; nt < 4; nt++) {
                int jc = nt * 8 + kofs;
                *(float2*)&xb[row0 * 36 + jc]       = make_float2(xacc[nt][0], xacc[nt][1]);
                *(float2*)&xb[(row0 + 8) * 36 + jc] = make_float2(xacc[nt][2], xacc[nt][3]);
            }
        }

        if (!ready) {
            while (ld_acq(&g_cntG[4 * kh]) < tgt) __nanosleep(32);
            issue_stage0();
        }

        float acc[4][4];
#pragma unroll
        for (int j = 0; j < 4; j++)
#pragma unroll
            for (int q = 0; q < 4; q++) acc[j][q] = 0.f;

#pragma unroll
        for (int gi = 0; gi < 4; gi++) {
            // first 4 iterations of stage gi (ready work hides the next poll)
#pragma unroll
            for (int i = 0; i < 4; i++) {
                const int it = gi * 8 + i;
                const int ca = it & 15, cb = it & 1;
                uint32_t ah[4] = {fA[ca].x, fA[ca].y, fA[ca].z, fA[ca].w};
                uint4 q0 = fB[cb][0], q1 = fB[cb][1];
                if (it + 2 < 32) loadB(cb, it + 2);
                MMAF16(acc[0], ah, q0.x, q0.y);
                MMAF16(acc[1], ah, q0.z, q0.w);
                MMAF16(acc[2], ah, q1.x, q1.y);
                MMAF16(acc[3], ah, q1.z, q1.w);
            }
            // poll next group mid-stage; issue its loads 4 iterations ahead
            if (gi < 3) {
                while (ld_acq(&g_cntG[4 * kh + gi + 1]) < tgt) __nanosleep(32);
#pragma unroll
                for (int i = 0; i < 8; i++) {
                    int it2 = (gi + 1) * 8 + i;
                    fA[it2 & 15] = __ldcg((const uint4*)(hs + (size_t)it2 * 512));
                }
            }
            // remaining 4 iterations of stage gi
#pragma unroll
            for (int i = 4; i < 8; i++) {
                const int it = gi * 8 + i;
                const int ca = it & 15, cb = it & 1;
                uint32_t ah[4] = {fA[ca].x, fA[ca].y, fA[ca].z, fA[ca].w};
                uint4 q0 = fB[cb][0], q1 = fB[cb][1];
                if (it + 2 < 32) loadB(cb, it + 2);
                MMAF16(acc[0], ah, q0.x, q0.y);
                MMAF16(acc[1], ah, q0.z, q0.w);
                MMAF16(acc[2], ah, q1.x, q1.y);
                MMAF16(acc[3], ah, q1.z, q1.w);
            }
        }

        {
            float* gb = (kh == 0) ? gbA : gbB;
#pragma unroll
            for (int j = 0; j < 4; j++) {
                int jc = j * 8 + kofs;
                *(float2*)&gb[row0 * 36 + jc]       = make_float2(acc[j][0], acc[j][1]);
                *(float2*)&gb[(row0 + 8) * 36 + jc] = make_float2(acc[j][2], acc[j][3]);
            }
        }
        __syncthreads();

        // fused gates / cell update; publish h quad, release-RED signal
        {
            int slot = t % 3;
            const float* xA = sm + 4608 + slot * 2304 + pb * 36 + cbase;
            const float* xB = xA + 6912;
            float4 xa0 = *(const float4*)xA;
            float4 xa1 = *(const float4*)(xA + 4);
            float4 xb0 = *(const float4*)xB;
            float4 xb1 = *(const float4*)(xB + 4);
            float4 a0 = *(const float4*)&gbA[pb * 36 + cbase];
            float4 a1 = *(const float4*)&gbA[pb * 36 + cbase + 4];
            float4 b0 = *(const float4*)&gbB[pb * 36 + cbase];
            float4 b1 = *(const float4*)&gbB[pb * 36 + cbase + 4];

            float p0 = xa0.x + xb0.x + a0.x + b0.x + bias0.x;
            float p1 = xa0.y + xb0.y + a0.y + b0.y + bias0.y;
            float p2 = xa0.z + xb0.z + a0.z + b0.z + bias0.z;
            float p3 = xa0.w + xb0.w + a0.w + b0.w + bias0.w;
            float nc0 = fsig(p0) * cr0 + fsig(p1) * fth(p3);
            float nh0 = fsig(p2) * fth(nc0);
            nh0 *= mk; nc0 *= mk;

            float q0 = xa1.x + xb1.x + a1.x + b1.x + bias1.x;
            float q1 = xa1.y + xb1.y + a1.y + b1.y + bias1.y;
            float q2 = xa1.z + xb1.z + a1.z + b1.z + bias1.z;
            float q3 = xa1.w + xb1.w + a1.w + b1.w + bias1.w;
            float nc1 = fsig(q0) * cr1 + fsig(q1) * fth(q3);
            float nh1 = fsig(q2) * fth(nc1);
            nh1 *= mk; nc1 *= mk;

            cr0 = nc0; cr1 = nc1;

            // publish split h (the only cross-CTA-consumed data)
            g_hf2[t & 1][widx] = f16pair(make_float2(nh0, nh1));
            __syncthreads();                      // orders all publishes before tid0's RED
            if (tid == 0) red_rel(&g_cntG[grp]);  // release-RED: no MEMBAR on the path

            // deferred output stores (not on the critical path)
            size_t oi = ((size_t)pb * Lsz + t) * Hsz + cg * 8 + hu;
            *(float2*)(outh + oi) = make_float2(nh0, nh1);
            *(float2*)(outc + oi) = make_float2(nc0, nc1);
        }
    }
}

// ---------------------------------------------------------------------------
extern "C" void kernel_launch(void* const* d_in, const int* in_sizes, int n_in,
                              void* d_out, int out_size)
{
    const float* x    = (const float*)d_in[0];
    const float* mask = (const float*)d_in[1];
    const float* Wf   = (const float*)d_in[2];
    const float* bf   = (const float*)d_in[3];
    const float* Wi   = (const float*)d_in[4];
    const float* bi   = (const float*)d_in[5];
    const float* Wo   = (const float*)d_in[6];
    const float* bo   = (const float*)d_in[7];
    const float* Wu   = (const float*)d_in[8];
    const float* bu   = (const float*)d_in[9];
    const float* h0   = (const float*)d_in[10];
    const float* c0   = (const float*)d_in[11];

    float* outh = (float*)d_out;
    float* outc = outh + (size_t)Bsz * Lsz * Hsz;

    cudaFuncSetAttribute(lstm_fused_kernel,
                         cudaFuncAttributeMaxDynamicSharedMemorySize,
                         SMEM_FLOATS * 4);

    pack_kernel<<<8192, 256>>>(Wf, Wi, Wo, Wu, bf, bi, bo, bu, h0);
    xsplit_kernel<<<32768, 256>>>(x);
    lstm_fused_kernel<<<NCTA, 256, SMEM_FLOATS * 4>>>(mask, c0, outh, outc);
}